// round 1
// baseline (speedup 1.0000x reference)
#include <cuda_runtime.h>
#include <math.h>

#define N_INST 128
#define NV     128
#define IMG    512
#define RES    64
#define NPIX   (RES*RES)            // 4096
#define SPLIT  4
#define THREADS2 256
#define PIX_PER_BLOCK (NPIX/SPLIT)  // 1024
#define PPT (PIX_PER_BLOCK/THREADS2) // 4
#define INV_S 0.1f

// Scratch (no allocations allowed)
__device__ float g_verts[N_INST*NV*2];
__device__ float g_ub[N_INST*4];
__device__ float g_part[N_INST*SPLIT*3];

// ---------------- Kernel 1: union box + normalized verts ----------------
__global__ __launch_bounds__(NV) void prep_kernel(const float* __restrict__ preds,
                                                  const float* __restrict__ bboxes) {
    int n = blockIdx.x;
    int v = threadIdx.x;
    float x = preds[(n*NV + v)*2 + 0];
    float y = preds[(n*NV + v)*2 + 1];

    __shared__ float sminx[NV], sminy[NV], smaxx[NV], smaxy[NV];
    sminx[v] = x; sminy[v] = y; smaxx[v] = x; smaxy[v] = y;
    __syncthreads();
    for (int s = NV/2; s > 0; s >>= 1) {
        if (v < s) {
            sminx[v] = fminf(sminx[v], sminx[v+s]);
            sminy[v] = fminf(sminy[v], sminy[v+s]);
            smaxx[v] = fmaxf(smaxx[v], smaxx[v+s]);
            smaxy[v] = fmaxf(smaxy[v], smaxy[v+s]);
        }
        __syncthreads();
    }
    __shared__ float ub[4];
    if (v == 0) {
        ub[0] = fminf(sminx[0], bboxes[n*4 + 0]);
        ub[1] = fminf(sminy[0], bboxes[n*4 + 1]);
        ub[2] = fmaxf(smaxx[0], bboxes[n*4 + 2]);
        ub[3] = fmaxf(smaxy[0], bboxes[n*4 + 3]);
        g_ub[n*4+0] = ub[0]; g_ub[n*4+1] = ub[1];
        g_ub[n*4+2] = ub[2]; g_ub[n*4+3] = ub[3];
    }
    __syncthreads();
    float vx = (x - ub[0]) / (ub[2] - ub[0]) * (float)RES - 0.5f;
    float vy = (y - ub[1]) / (ub[3] - ub[1]) * (float)RES - 0.5f;
    g_verts[(n*NV + v)*2 + 0] = vx;
    g_verts[(n*NV + v)*2 + 1] = vy;
}

// ---------------- Kernel 2: rasterize + target sample + dice partials ----------------
__global__ __launch_bounds__(THREADS2) void raster_kernel(const float* __restrict__ masks) {
    int b     = blockIdx.x;
    int n     = b / SPLIT;
    int chunk = b % SPLIT;
    int tid   = threadIdx.x;

    __shared__ float s_ax[NV], s_ay[NV], s_abx[NV], s_aby[NV];
    __shared__ float s_invd[NV], s_slope[NV], s_by[NV];
    __shared__ float s_ub[4];

    if (tid < 4) s_ub[tid] = g_ub[n*4 + tid];
    if (tid < NV) {
        float ax = g_verts[(n*NV + tid)*2 + 0];
        float ay = g_verts[(n*NV + tid)*2 + 1];
        int t1 = (tid + 1) & (NV - 1);
        float bx = g_verts[(n*NV + t1)*2 + 0];
        float by = g_verts[(n*NV + t1)*2 + 1];
        float abx = bx - ax, aby = by - ay;
        s_ax[tid]  = ax;  s_ay[tid]  = ay;
        s_abx[tid] = abx; s_aby[tid] = aby;
        s_invd[tid] = 1.0f / (abx*abx + aby*aby + 1e-12f);
        float sdy = (aby == 0.0f) ? 1.0f : aby;
        s_slope[tid] = abx / sdy;
        s_by[tid] = by;
    }
    __syncthreads();

    int pbase = chunk * PIX_PER_BLOCK;
    float pxf[PPT], pyf[PPT], d2min[PPT];
    int   cross[PPT];
#pragma unroll
    for (int k = 0; k < PPT; k++) {
        int p = pbase + tid + k*THREADS2;
        pxf[k] = (float)(p & (RES-1));
        pyf[k] = (float)(p >> 6);
        d2min[k] = 3.4e38f;
        cross[k] = 0;
    }

    // Segment loop — params broadcast from SMEM, 4 pixels in registers
    for (int v = 0; v < NV; v++) {
        float ax = s_ax[v],  ay = s_ay[v];
        float abx = s_abx[v], aby = s_aby[v];
        float invd = s_invd[v], slope = s_slope[v], by = s_by[v];
#pragma unroll
        for (int k = 0; k < PPT; k++) {
            float pax = pxf[k] - ax;
            float pay = pyf[k] - ay;
            float t = (pax*abx + pay*aby) * invd;
            t = fminf(fmaxf(t, 0.0f), 1.0f);
            float dx = pax - t*abx;
            float dy = pay - t*aby;
            float d2 = dx*dx + dy*dy;
            d2min[k] = fminf(d2min[k], d2);
            bool cond = (ay > pyf[k]) != (by > pyf[k]);
            float xint = ax + (pyf[k] - ay) * slope;
            cross[k] += (cond && (pxf[k] < xint)) ? 1 : 0;
        }
    }

    // Sigmoid + clip, target bilinear + threshold, dice partials
    float ub0 = s_ub[0], ub1 = s_ub[1], ub2 = s_ub[2], ub3 = s_ub[3];
    const float* __restrict__ mask = masks + (size_t)n * IMG * IMG;
    float inter = 0.0f, sp = 0.0f, st = 0.0f;
#pragma unroll
    for (int k = 0; k < PPT; k++) {
        int p = pbase + tid + k*THREADS2;
        float sign = (cross[k] & 1) ? 1.0f : -1.0f;
        float xarg = sign * d2min[k] * INV_S;
        float pred = 1.0f / (1.0f + __expf(-xarg));
        pred = fminf(fmaxf(pred, 1e-5f), 0.99999f);

        int j = p & (RES-1);
        int i = p >> 6;
        float xs = ub0 + (ub2 - ub0) * (((float)j + 0.5f) * (1.0f/(float)RES)) - 0.5f;
        float ys = ub1 + (ub3 - ub1) * (((float)i + 0.5f) * (1.0f/(float)RES)) - 0.5f;
        float x0 = floorf(xs), y0 = floorf(ys);
        float wx = xs - x0,    wy = ys - y0;
        int x0i = min(max((int)x0, 0), IMG-1);
        int x1i = min(x0i + 1, IMG-1);
        int y0i = min(max((int)y0, 0), IMG-1);
        int y1i = min(y0i + 1, IMG-1);
        float m00 = mask[y0i*IMG + x0i];
        float m01 = mask[y0i*IMG + x1i];
        float m10 = mask[y1i*IMG + x0i];
        float m11 = mask[y1i*IMG + x1i];
        float val = (1.0f - wy) * ((1.0f - wx)*m00 + wx*m01)
                  +          wy * ((1.0f - wx)*m10 + wx*m11);
        float tgt = (val >= 0.5f) ? 1.0f : 0.0f;

        inter += pred * tgt;
        sp    += pred;
        st    += tgt;
    }

    // Deterministic block reduce (warp shuffle + shared)
    unsigned fullmask = 0xFFFFFFFFu;
#pragma unroll
    for (int o = 16; o > 0; o >>= 1) {
        inter += __shfl_down_sync(fullmask, inter, o);
        sp    += __shfl_down_sync(fullmask, sp,    o);
        st    += __shfl_down_sync(fullmask, st,    o);
    }
    __shared__ float r_inter[THREADS2/32], r_sp[THREADS2/32], r_st[THREADS2/32];
    int wid = tid >> 5, lid = tid & 31;
    if (lid == 0) { r_inter[wid] = inter; r_sp[wid] = sp; r_st[wid] = st; }
    __syncthreads();
    if (tid == 0) {
        float ti = 0.0f, tp = 0.0f, tt = 0.0f;
#pragma unroll
        for (int w = 0; w < THREADS2/32; w++) { ti += r_inter[w]; tp += r_sp[w]; tt += r_st[w]; }
        int slot = (n*SPLIT + chunk)*3;
        g_part[slot+0] = ti;
        g_part[slot+1] = tp;
        g_part[slot+2] = tt;
    }
}

// ---------------- Kernel 3: per-instance dice + final mean ----------------
__global__ __launch_bounds__(N_INST) void finalize_kernel(float* __restrict__ out) {
    int n = threadIdx.x;
    float inter = 0.0f, sp = 0.0f, st = 0.0f;
#pragma unroll
    for (int c = 0; c < SPLIT; c++) {
        int slot = (n*SPLIT + c)*3;
        inter += g_part[slot+0];
        sp    += g_part[slot+1];
        st    += g_part[slot+2];
    }
    float loss = 1.0f - (2.0f*inter + 1.0f) / (sp + st + 1.0f);
    __shared__ float s[N_INST];
    s[n] = loss;
    __syncthreads();
    for (int o = N_INST/2; o > 0; o >>= 1) {
        if (n < o) s[n] += s[n+o];
        __syncthreads();
    }
    if (n == 0) out[0] = s[0] * (1.0f / (float)N_INST);
}

extern "C" void kernel_launch(void* const* d_in, const int* in_sizes, int n_in,
                              void* d_out, int out_size) {
    const float* preds  = (const float*)d_in[0];
    const float* masks  = (const float*)d_in[1];
    const float* bboxes = (const float*)d_in[2];
    float* out = (float*)d_out;

    prep_kernel<<<N_INST, NV>>>(preds, bboxes);
    raster_kernel<<<N_INST*SPLIT, THREADS2>>>(masks);
    finalize_kernel<<<1, N_INST>>>(out);
}

// round 2
// speedup vs baseline: 1.0517x; 1.0517x over previous
#include <cuda_runtime.h>
#include <math.h>

#define N_INST 128
#define NV     128
#define IMG    512
#define RES    64
#define NPIX   (RES*RES)            // 4096
#define SPLIT  4
#define THREADS2 256
#define PIX_PER_BLOCK (NPIX/SPLIT)  // 1024
#define PPT (PIX_PER_BLOCK/THREADS2) // 4
#define INV_S 0.1f

// Scratch (no allocations allowed)
__device__ float g_verts[N_INST*NV*2];
__device__ float g_ub[N_INST*4];
__device__ float g_part[N_INST*SPLIT*3];

// ---------------- Kernel 1: union box + normalized verts ----------------
__global__ __launch_bounds__(NV) void prep_kernel(const float* __restrict__ preds,
                                                  const float* __restrict__ bboxes) {
    int n = blockIdx.x;
    int v = threadIdx.x;
    float x = preds[(n*NV + v)*2 + 0];
    float y = preds[(n*NV + v)*2 + 1];

    __shared__ float sminx[NV], sminy[NV], smaxx[NV], smaxy[NV];
    sminx[v] = x; sminy[v] = y; smaxx[v] = x; smaxy[v] = y;
    __syncthreads();
    for (int s = NV/2; s > 0; s >>= 1) {
        if (v < s) {
            sminx[v] = fminf(sminx[v], sminx[v+s]);
            sminy[v] = fminf(sminy[v], sminy[v+s]);
            smaxx[v] = fmaxf(smaxx[v], smaxx[v+s]);
            smaxy[v] = fmaxf(smaxy[v], smaxy[v+s]);
        }
        __syncthreads();
    }
    __shared__ float ub[4];
    if (v == 0) {
        ub[0] = fminf(sminx[0], bboxes[n*4 + 0]);
        ub[1] = fminf(sminy[0], bboxes[n*4 + 1]);
        ub[2] = fmaxf(smaxx[0], bboxes[n*4 + 2]);
        ub[3] = fmaxf(smaxy[0], bboxes[n*4 + 3]);
        g_ub[n*4+0] = ub[0]; g_ub[n*4+1] = ub[1];
        g_ub[n*4+2] = ub[2]; g_ub[n*4+3] = ub[3];
    }
    __syncthreads();
    float vx = (x - ub[0]) / (ub[2] - ub[0]) * (float)RES - 0.5f;
    float vy = (y - ub[1]) / (ub[3] - ub[1]) * (float)RES - 0.5f;
    g_verts[(n*NV + v)*2 + 0] = vx;
    g_verts[(n*NV + v)*2 + 1] = vy;
}

// ---------------- Kernel 2: rasterize + target sample + dice partials ----------------
__global__ __launch_bounds__(THREADS2) void raster_kernel(const float* __restrict__ masks) {
    int b     = blockIdx.x;
    int n     = b / SPLIT;
    int chunk = b % SPLIT;
    int tid   = threadIdx.x;

    __shared__ float s_ax[NV], s_ay[NV], s_abx[NV], s_aby[NV];
    __shared__ float s_invd[NV], s_slope[NV], s_by[NV];
    __shared__ float s_ub[4];

    if (tid < 4) s_ub[tid] = g_ub[n*4 + tid];
    if (tid < NV) {
        float ax = g_verts[(n*NV + tid)*2 + 0];
        float ay = g_verts[(n*NV + tid)*2 + 1];
        int t1 = (tid + 1) & (NV - 1);
        float bx = g_verts[(n*NV + t1)*2 + 0];
        float by = g_verts[(n*NV + t1)*2 + 1];
        float abx = bx - ax, aby = by - ay;
        s_ax[tid]  = ax;  s_ay[tid]  = ay;
        s_abx[tid] = abx; s_aby[tid] = aby;
        s_invd[tid] = 1.0f / (abx*abx + aby*aby + 1e-12f);
        float sdy = (aby == 0.0f) ? 1.0f : aby;
        s_slope[tid] = abx / sdy;
        s_by[tid] = by;
    }
    __syncthreads();

    int pbase = chunk * PIX_PER_BLOCK;
    float pxf[PPT], pyf[PPT], d2min[PPT];
    int   cross[PPT];
#pragma unroll
    for (int k = 0; k < PPT; k++) {
        int p = pbase + tid + k*THREADS2;
        pxf[k] = (float)(p & (RES-1));
        pyf[k] = (float)(p >> 6);
        d2min[k] = 3.4e38f;
        cross[k] = 0;
    }

    // Segment loop — params broadcast from SMEM, 4 pixels in registers
    for (int v = 0; v < NV; v++) {
        float ax = s_ax[v],  ay = s_ay[v];
        float abx = s_abx[v], aby = s_aby[v];
        float invd = s_invd[v], slope = s_slope[v], by = s_by[v];
#pragma unroll
        for (int k = 0; k < PPT; k++) {
            float pax = pxf[k] - ax;
            float pay = pyf[k] - ay;
            float t = (pax*abx + pay*aby) * invd;
            t = fminf(fmaxf(t, 0.0f), 1.0f);
            float dx = pax - t*abx;
            float dy = pay - t*aby;
            float d2 = dx*dx + dy*dy;
            d2min[k] = fminf(d2min[k], d2);
            bool cond = (ay > pyf[k]) != (by > pyf[k]);
            float xint = ax + (pyf[k] - ay) * slope;
            cross[k] += (cond && (pxf[k] < xint)) ? 1 : 0;
        }
    }

    // Sigmoid + clip, target bilinear + threshold, dice partials
    float ub0 = s_ub[0], ub1 = s_ub[1], ub2 = s_ub[2], ub3 = s_ub[3];
    const float* __restrict__ mask = masks + (size_t)n * IMG * IMG;
    float inter = 0.0f, sp = 0.0f, st = 0.0f;
#pragma unroll
    for (int k = 0; k < PPT; k++) {
        int p = pbase + tid + k*THREADS2;
        float sign = (cross[k] & 1) ? 1.0f : -1.0f;
        float xarg = sign * d2min[k] * INV_S;
        float pred = 1.0f / (1.0f + __expf(-xarg));
        pred = fminf(fmaxf(pred, 1e-5f), 0.99999f);

        int j = p & (RES-1);
        int i = p >> 6;
        float xs = ub0 + (ub2 - ub0) * (((float)j + 0.5f) * (1.0f/(float)RES)) - 0.5f;
        float ys = ub1 + (ub3 - ub1) * (((float)i + 0.5f) * (1.0f/(float)RES)) - 0.5f;
        float x0 = floorf(xs), y0 = floorf(ys);
        float wx = xs - x0,    wy = ys - y0;
        int x0i = min(max((int)x0, 0), IMG-1);
        int x1i = min(x0i + 1, IMG-1);
        int y0i = min(max((int)y0, 0), IMG-1);
        int y1i = min(y0i + 1, IMG-1);
        float m00 = mask[y0i*IMG + x0i];
        float m01 = mask[y0i*IMG + x1i];
        float m10 = mask[y1i*IMG + x0i];
        float m11 = mask[y1i*IMG + x1i];
        float val = (1.0f - wy) * ((1.0f - wx)*m00 + wx*m01)
                  +          wy * ((1.0f - wx)*m10 + wx*m11);
        float tgt = (val >= 0.5f) ? 1.0f : 0.0f;

        inter += pred * tgt;
        sp    += pred;
        st    += tgt;
    }

    // Deterministic block reduce (warp shuffle + shared)
    unsigned fullmask = 0xFFFFFFFFu;
#pragma unroll
    for (int o = 16; o > 0; o >>= 1) {
        inter += __shfl_down_sync(fullmask, inter, o);
        sp    += __shfl_down_sync(fullmask, sp,    o);
        st    += __shfl_down_sync(fullmask, st,    o);
    }
    __shared__ float r_inter[THREADS2/32], r_sp[THREADS2/32], r_st[THREADS2/32];
    int wid = tid >> 5, lid = tid & 31;
    if (lid == 0) { r_inter[wid] = inter; r_sp[wid] = sp; r_st[wid] = st; }
    __syncthreads();
    if (tid == 0) {
        float ti = 0.0f, tp = 0.0f, tt = 0.0f;
#pragma unroll
        for (int w = 0; w < THREADS2/32; w++) { ti += r_inter[w]; tp += r_sp[w]; tt += r_st[w]; }
        int slot = (n*SPLIT + chunk)*3;
        g_part[slot+0] = ti;
        g_part[slot+1] = tp;
        g_part[slot+2] = tt;
    }
}

// ---------------- Kernel 3: per-instance dice + final mean ----------------
__global__ __launch_bounds__(N_INST) void finalize_kernel(float* __restrict__ out) {
    int n = threadIdx.x;
    float inter = 0.0f, sp = 0.0f, st = 0.0f;
#pragma unroll
    for (int c = 0; c < SPLIT; c++) {
        int slot = (n*SPLIT + c)*3;
        inter += g_part[slot+0];
        sp    += g_part[slot+1];
        st    += g_part[slot+2];
    }
    float loss = 1.0f - (2.0f*inter + 1.0f) / (sp + st + 1.0f);
    __shared__ float s[N_INST];
    s[n] = loss;
    __syncthreads();
    for (int o = N_INST/2; o > 0; o >>= 1) {
        if (n < o) s[n] += s[n+o];
        __syncthreads();
    }
    if (n == 0) out[0] = s[0] * (1.0f / (float)N_INST);
}

extern "C" void kernel_launch(void* const* d_in, const int* in_sizes, int n_in,
                              void* d_out, int out_size) {
    const float* preds  = (const float*)d_in[0];
    const float* masks  = (const float*)d_in[1];
    const float* bboxes = (const float*)d_in[2];
    float* out = (float*)d_out;

    prep_kernel<<<N_INST, NV>>>(preds, bboxes);
    raster_kernel<<<N_INST*SPLIT, THREADS2>>>(masks);
    finalize_kernel<<<1, N_INST>>>(out);
}

// round 3
// speedup vs baseline: 1.5710x; 1.4938x over previous
#include <cuda_runtime.h>
#include <math.h>

#define N_INST 128
#define NV     128
#define IMG    512
#define RES    64
#define SPLIT  4                    // 4 blocks per instance, 16 rows each
#define THREADS 128
#define PPT     8                   // 8 consecutive x per thread (one row)
#define NBLOCKS (N_INST*SPLIT)      // 512
#define INV_S   0.1f

// Scratch (no allocations allowed)
__device__ float g_part[NBLOCKS*3];
__device__ int   g_count = 0;

__global__ __launch_bounds__(THREADS) void fused_kernel(
    const float* __restrict__ preds,
    const float* __restrict__ masks,
    const float* __restrict__ bboxes,
    float* __restrict__ out)
{
    int b     = blockIdx.x;
    int n     = b >> 2;
    int chunk = b & 3;
    int tid   = threadIdx.x;
    int wid   = tid >> 5, lid = tid & 31;

    __shared__ float s_ax[NV], s_ay[NV], s_abx[NV], s_aby[NV];
    __shared__ float s_invd[NV], s_slope[NV], s_by[NV];
    __shared__ float s_vx[NV], s_vy[NV];
    __shared__ float s_red[16];
    __shared__ float s_ub[4];
    __shared__ int   s_last;

    // ---- per-block prep: union box + normalized verts + segment params ----
    float2 pv = ((const float2*)preds)[n*NV + tid];
    float x = pv.x, y = pv.y;
    float mnx = x, mny = y, mxx = x, mxy = y;
#pragma unroll
    for (int o = 16; o > 0; o >>= 1) {
        mnx = fminf(mnx, __shfl_xor_sync(0xffffffffu, mnx, o));
        mny = fminf(mny, __shfl_xor_sync(0xffffffffu, mny, o));
        mxx = fmaxf(mxx, __shfl_xor_sync(0xffffffffu, mxx, o));
        mxy = fmaxf(mxy, __shfl_xor_sync(0xffffffffu, mxy, o));
    }
    if (lid == 0) { s_red[wid] = mnx; s_red[4+wid] = mny; s_red[8+wid] = mxx; s_red[12+wid] = mxy; }
    __syncthreads();
    if (tid == 0) {
        float a = fminf(fminf(s_red[0],  s_red[1]),  fminf(s_red[2],  s_red[3]));
        float c = fminf(fminf(s_red[4],  s_red[5]),  fminf(s_red[6],  s_red[7]));
        float d = fmaxf(fmaxf(s_red[8],  s_red[9]),  fmaxf(s_red[10], s_red[11]));
        float e = fmaxf(fmaxf(s_red[12], s_red[13]), fmaxf(s_red[14], s_red[15]));
        s_ub[0] = fminf(a, bboxes[n*4+0]);
        s_ub[1] = fminf(c, bboxes[n*4+1]);
        s_ub[2] = fmaxf(d, bboxes[n*4+2]);
        s_ub[3] = fmaxf(e, bboxes[n*4+3]);
    }
    __syncthreads();
    float ub0 = s_ub[0], ub1 = s_ub[1], ub2 = s_ub[2], ub3 = s_ub[3];
    float vx = (x - ub0) / (ub2 - ub0) * (float)RES - 0.5f;
    float vy = (y - ub1) / (ub3 - ub1) * (float)RES - 0.5f;
    s_vx[tid] = vx; s_vy[tid] = vy;
    __syncthreads();
    {
        int t1 = (tid + 1) & (NV - 1);
        float ax = vx, ay = vy;
        float bx = s_vx[t1], byv = s_vy[t1];
        float abx = bx - ax, aby = byv - ay;
        s_ax[tid]  = ax;  s_ay[tid]  = ay;
        s_abx[tid] = abx; s_aby[tid] = aby;
        s_invd[tid]  = 1.0f / (abx*abx + aby*aby + 1e-12f);
        float sdy = (aby == 0.0f) ? 1.0f : aby;
        s_slope[tid] = abx / sdy;
        s_by[tid] = byv;
    }
    __syncthreads();

    // ---- rasterize: one row of 8 consecutive pixels per thread ----
    int row   = chunk * 16 + (tid >> 3);
    int xbase = (tid & 7) * PPT;
    float pyf  = (float)row;
    float xbf  = (float)xbase;

    float pxf[PPT], d2min[PPT];
#pragma unroll
    for (int k = 0; k < PPT; k++) { pxf[k] = xbf + (float)k; d2min[k] = 3.4e38f; }
    unsigned crossbits = 0;

    for (int v = 0; v < NV; v++) {
        float ax = s_ax[v],  ay = s_ay[v];
        float abx = s_abx[v], aby = s_aby[v];
        float invd = s_invd[v], slope = s_slope[v], byv = s_by[v];

        float pay    = pyf - ay;
        float payaby = pay * aby;
        bool  cond   = (ay > pyf) != (byv > pyf);
        float xint   = fmaf(pay, slope, ax);
        int   kk     = (int)ceilf(xint - xbf);
        kk = min(max(kk, 0), PPT);
        unsigned m   = (1u << kk) - 1u;
        crossbits ^= cond ? m : 0u;

#pragma unroll
        for (int k = 0; k < PPT; k++) {
            float pax = pxf[k] - ax;
            float t = fmaf(pax, abx, payaby) * invd;
            t = fminf(fmaxf(t, 0.0f), 1.0f);
            float dx = fmaf(-t, abx, pax);
            float dy = fmaf(-t, aby, pay);
            float d2 = fmaf(dx, dx, dy*dy);
            d2min[k] = fminf(d2min[k], d2);
        }
    }

    // ---- sigmoid + target bilinear + dice partials ----
    const float* __restrict__ mask = masks + (size_t)n * IMG * IMG;
    float ys = ub1 + (ub3 - ub1) * ((pyf + 0.5f) * (1.0f/(float)RES)) - 0.5f;
    float y0 = floorf(ys);
    float wy = ys - y0;
    int y0i = min(max((int)y0, 0), IMG-1);
    int y1i = min(y0i + 1, IMG-1);
    const float* r0 = mask + y0i*IMG;
    const float* r1 = mask + y1i*IMG;

    float inter = 0.0f, sp = 0.0f, st = 0.0f;
#pragma unroll
    for (int k = 0; k < PPT; k++) {
        float sign = (crossbits >> k) & 1u ? 1.0f : -1.0f;
        float xarg = sign * d2min[k] * INV_S;
        float pred = 1.0f / (1.0f + __expf(-xarg));
        pred = fminf(fmaxf(pred, 1e-5f), 0.99999f);

        float xs = ub0 + (ub2 - ub0) * ((pxf[k] + 0.5f) * (1.0f/(float)RES)) - 0.5f;
        float x0 = floorf(xs);
        float wx = xs - x0;
        int x0i = min(max((int)x0, 0), IMG-1);
        int x1i = min(x0i + 1, IMG-1);
        float m00 = r0[x0i], m01 = r0[x1i];
        float m10 = r1[x0i], m11 = r1[x1i];
        float val = (1.0f - wy) * ((1.0f - wx)*m00 + wx*m01)
                  +          wy * ((1.0f - wx)*m10 + wx*m11);
        float tgt = (val >= 0.5f) ? 1.0f : 0.0f;

        inter += pred * tgt;
        sp    += pred;
        st    += tgt;
    }

    // ---- deterministic block reduce ----
#pragma unroll
    for (int o = 16; o > 0; o >>= 1) {
        inter += __shfl_down_sync(0xffffffffu, inter, o);
        sp    += __shfl_down_sync(0xffffffffu, sp,    o);
        st    += __shfl_down_sync(0xffffffffu, st,    o);
    }
    __shared__ float r_i[4], r_p[4], r_t[4];
    if (lid == 0) { r_i[wid] = inter; r_p[wid] = sp; r_t[wid] = st; }
    __syncthreads();
    if (tid == 0) {
        float ti = r_i[0]+r_i[1]+r_i[2]+r_i[3];
        float tp = r_p[0]+r_p[1]+r_p[2]+r_p[3];
        float tt = r_t[0]+r_t[1]+r_t[2]+r_t[3];
        g_part[b*3+0] = ti;
        g_part[b*3+1] = tp;
        g_part[b*3+2] = tt;
        __threadfence();
        int old = atomicAdd(&g_count, 1);
        s_last = (old == NBLOCKS - 1) ? 1 : 0;
    }
    __syncthreads();

    // ---- last block finalizes: per-instance dice + mean ----
    if (s_last) {
        float fi = 0.0f, fp = 0.0f, ft = 0.0f;   // instance = tid
#pragma unroll
        for (int c = 0; c < SPLIT; c++) {
            int slot = ((tid << 2) + c) * 3;
            fi += __ldcg(&g_part[slot+0]);
            fp += __ldcg(&g_part[slot+1]);
            ft += __ldcg(&g_part[slot+2]);
        }
        float loss = 1.0f - (2.0f*fi + 1.0f) / (fp + ft + 1.0f);
        s_vx[tid] = loss;                        // reuse smem as scratch
        __syncthreads();
        for (int o = THREADS/2; o > 0; o >>= 1) {
            if (tid < o) s_vx[tid] += s_vx[tid + o];
            __syncthreads();
        }
        if (tid == 0) {
            out[0] = s_vx[0] * (1.0f / (float)N_INST);
            g_count = 0;                          // reset for next graph replay
        }
    }
}

extern "C" void kernel_launch(void* const* d_in, const int* in_sizes, int n_in,
                              void* d_out, int out_size) {
    const float* preds  = (const float*)d_in[0];
    const float* masks  = (const float*)d_in[1];
    const float* bboxes = (const float*)d_in[2];
    float* out = (float*)d_out;

    fused_kernel<<<NBLOCKS, THREADS>>>(preds, masks, bboxes, out);
}

// round 4
// speedup vs baseline: 1.8442x; 1.1739x over previous
#include <cuda_runtime.h>
#include <math.h>

#define N_INST 128
#define NV     128
#define IMG    512
#define RES    64
#define SPLIT  4                    // 4 blocks per instance, 16 rows each
#define THREADS 128
#define PPT     8                   // 8 consecutive x per thread (one row)
#define NPAIR   (PPT/2)
#define NBLOCKS (N_INST*SPLIT)      // 512
#define INV_S   0.1f

typedef unsigned long long ull;

__device__ __forceinline__ ull f2add(ull a, ull b) {
    ull r; asm("add.rn.f32x2 %0,%1,%2;" : "=l"(r) : "l"(a), "l"(b)); return r;
}
__device__ __forceinline__ ull f2mul(ull a, ull b) {
    ull r; asm("mul.rn.f32x2 %0,%1,%2;" : "=l"(r) : "l"(a), "l"(b)); return r;
}
__device__ __forceinline__ ull f2fma(ull a, ull b, ull c) {
    ull r; asm("fma.rn.f32x2 %0,%1,%2,%3;" : "=l"(r) : "l"(a), "l"(b), "l"(c)); return r;
}
__device__ __forceinline__ ull fpack(float lo, float hi) {
    ull r; asm("mov.b64 %0,{%1,%2};" : "=l"(r) : "f"(lo), "f"(hi)); return r;
}
__device__ __forceinline__ void funpack(float& lo, float& hi, ull v) {
    asm("mov.b64 {%0,%1},%2;" : "=f"(lo), "=f"(hi) : "l"(v));
}
__device__ __forceinline__ float mulsat(float a, float b) {
    float r; asm("mul.rn.sat.f32 %0,%1,%2;" : "=f"(r) : "f"(a), "f"(b)); return r;
}

// Scratch (no allocations allowed)
__device__ float g_part[NBLOCKS*3];
__device__ int   g_count = 0;

__global__ __launch_bounds__(THREADS) void fused_kernel(
    const float* __restrict__ preds,
    const float* __restrict__ masks,
    const float* __restrict__ bboxes,
    float* __restrict__ out)
{
    int b     = blockIdx.x;
    int n     = b >> 2;
    int chunk = b & 3;
    int tid   = threadIdx.x;
    int wid   = tid >> 5, lid = tid & 31;

    __shared__ float4 s_pk0[NV];   // {-ax,-ax, abx,abx}
    __shared__ float4 s_pk1[NV];   // {-abx,-abx, -aby,-aby}
    __shared__ float4 s_sc[NV];    // {ay, aby, invd, by}
    __shared__ float2 s_par[NV];   // {slope, ax}
    __shared__ float  s_vx[NV], s_vy[NV];
    __shared__ float  s_red[16];
    __shared__ float  s_ub[4];
    __shared__ int    s_last;

    // ---- per-block prep: union box + normalized verts + segment params ----
    float2 pv = ((const float2*)preds)[n*NV + tid];
    float x = pv.x, y = pv.y;
    float mnx = x, mny = y, mxx = x, mxy = y;
#pragma unroll
    for (int o = 16; o > 0; o >>= 1) {
        mnx = fminf(mnx, __shfl_xor_sync(0xffffffffu, mnx, o));
        mny = fminf(mny, __shfl_xor_sync(0xffffffffu, mny, o));
        mxx = fmaxf(mxx, __shfl_xor_sync(0xffffffffu, mxx, o));
        mxy = fmaxf(mxy, __shfl_xor_sync(0xffffffffu, mxy, o));
    }
    if (lid == 0) { s_red[wid] = mnx; s_red[4+wid] = mny; s_red[8+wid] = mxx; s_red[12+wid] = mxy; }
    __syncthreads();
    if (tid == 0) {
        float a = fminf(fminf(s_red[0],  s_red[1]),  fminf(s_red[2],  s_red[3]));
        float c = fminf(fminf(s_red[4],  s_red[5]),  fminf(s_red[6],  s_red[7]));
        float d = fmaxf(fmaxf(s_red[8],  s_red[9]),  fmaxf(s_red[10], s_red[11]));
        float e = fmaxf(fmaxf(s_red[12], s_red[13]), fmaxf(s_red[14], s_red[15]));
        s_ub[0] = fminf(a, bboxes[n*4+0]);
        s_ub[1] = fminf(c, bboxes[n*4+1]);
        s_ub[2] = fmaxf(d, bboxes[n*4+2]);
        s_ub[3] = fmaxf(e, bboxes[n*4+3]);
    }
    __syncthreads();
    float ub0 = s_ub[0], ub1 = s_ub[1], ub2 = s_ub[2], ub3 = s_ub[3];
    float vx = (x - ub0) / (ub2 - ub0) * (float)RES - 0.5f;
    float vy = (y - ub1) / (ub3 - ub1) * (float)RES - 0.5f;
    s_vx[tid] = vx; s_vy[tid] = vy;
    __syncthreads();
    {
        int t1 = (tid + 1) & (NV - 1);
        float ax = vx, ay = vy;
        float bx = s_vx[t1], byv = s_vy[t1];
        float abx = bx - ax, aby = byv - ay;
        float invd = 1.0f / (abx*abx + aby*aby + 1e-12f);
        float sdy = (aby == 0.0f) ? 1.0f : aby;
        s_pk0[tid] = make_float4(-ax, -ax, abx, abx);
        s_pk1[tid] = make_float4(-abx, -abx, -aby, -aby);
        s_sc[tid]  = make_float4(ay, aby, invd, byv);
        s_par[tid] = make_float2(abx / sdy, ax);
    }
    __syncthreads();

    // ---- rasterize: one row of 8 consecutive pixels per thread ----
    int row   = chunk * 16 + (tid >> 3);
    int xbase = (tid & 7) * PPT;
    float pyf = (float)row;
    float xbf = (float)xbase;

    ull px2[NPAIR];
    float d2min[PPT];
#pragma unroll
    for (int j = 0; j < NPAIR; j++)
        px2[j] = fpack(xbf + (float)(2*j), xbf + (float)(2*j+1));
#pragma unroll
    for (int k = 0; k < PPT; k++) d2min[k] = 3.4e38f;
    unsigned crossbits = 0;

    for (int v = 0; v < NV; v++) {
        float4 p0 = s_pk0[v];
        float4 p1 = s_pk1[v];
        float4 sc = s_sc[v];
        float2 pr = s_par[v];
        ull nax2  = fpack(p0.x, p0.y);
        ull abx2  = fpack(p0.z, p0.w);
        ull nabx2 = fpack(p1.x, p1.y);
        ull naby2 = fpack(p1.z, p1.w);
        float ay = sc.x, aby = sc.y, invd = sc.z, byv = sc.w;
        float slope = pr.x, ax = pr.y;

        float pay    = pyf - ay;
        float payaby = pay * aby;
        ull pay2     = fpack(pay, pay);
        ull payaby2  = fpack(payaby, payaby);

        // parity (once per thread per segment)
        bool  cond = (ay > pyf) != (byv > pyf);
        float xint = fmaf(pay, slope, ax);
        int   kk   = (int)ceilf(xint - xbf);
        kk = min(max(kk, 0), PPT);
        unsigned m = (1u << kk) - 1u;
        crossbits ^= cond ? m : 0u;

        // packed distance (2 pixels per iteration)
#pragma unroll
        for (int j = 0; j < NPAIR; j++) {
            ull pax2 = f2add(px2[j], nax2);
            ull dot2 = f2fma(pax2, abx2, payaby2);
            float d0, d1; funpack(d0, d1, dot2);
            float t0 = mulsat(d0, invd);
            float t1 = mulsat(d1, invd);
            ull tc2 = fpack(t0, t1);
            ull dx2 = f2fma(tc2, nabx2, pax2);
            ull dy2 = f2fma(tc2, naby2, pay2);
            ull e2  = f2mul(dy2, dy2);
            ull q2  = f2fma(dx2, dx2, e2);
            float q0, q1; funpack(q0, q1, q2);
            d2min[2*j]   = fminf(d2min[2*j],   q0);
            d2min[2*j+1] = fminf(d2min[2*j+1], q1);
        }
    }

    // ---- sigmoid + target bilinear + dice partials ----
    const float* __restrict__ mask = masks + (size_t)n * IMG * IMG;
    float ys = ub1 + (ub3 - ub1) * ((pyf + 0.5f) * (1.0f/(float)RES)) - 0.5f;
    float y0 = floorf(ys);
    float wy = ys - y0;
    int y0i = min(max((int)y0, 0), IMG-1);
    int y1i = min(y0i + 1, IMG-1);
    const float* r0 = mask + y0i*IMG;
    const float* r1 = mask + y1i*IMG;

    float inter = 0.0f, sp = 0.0f, st = 0.0f;
#pragma unroll
    for (int k = 0; k < PPT; k++) {
        float sign = (crossbits >> k) & 1u ? 1.0f : -1.0f;
        float xarg = sign * d2min[k] * INV_S;
        float pred = 1.0f / (1.0f + __expf(-xarg));
        pred = fminf(fmaxf(pred, 1e-5f), 0.99999f);

        float xs = ub0 + (ub2 - ub0) * ((xbf + (float)k + 0.5f) * (1.0f/(float)RES)) - 0.5f;
        float x0 = floorf(xs);
        float wx = xs - x0;
        int x0i = min(max((int)x0, 0), IMG-1);
        int x1i = min(x0i + 1, IMG-1);
        float m00 = r0[x0i], m01 = r0[x1i];
        float m10 = r1[x0i], m11 = r1[x1i];
        float val = (1.0f - wy) * ((1.0f - wx)*m00 + wx*m01)
                  +          wy * ((1.0f - wx)*m10 + wx*m11);
        float tgt = (val >= 0.5f) ? 1.0f : 0.0f;

        inter += pred * tgt;
        sp    += pred;
        st    += tgt;
    }

    // ---- deterministic block reduce ----
#pragma unroll
    for (int o = 16; o > 0; o >>= 1) {
        inter += __shfl_down_sync(0xffffffffu, inter, o);
        sp    += __shfl_down_sync(0xffffffffu, sp,    o);
        st    += __shfl_down_sync(0xffffffffu, st,    o);
    }
    __shared__ float r_i[4], r_p[4], r_t[4];
    if (lid == 0) { r_i[wid] = inter; r_p[wid] = sp; r_t[wid] = st; }
    __syncthreads();
    if (tid == 0) {
        float ti = r_i[0]+r_i[1]+r_i[2]+r_i[3];
        float tp = r_p[0]+r_p[1]+r_p[2]+r_p[3];
        float tt = r_t[0]+r_t[1]+r_t[2]+r_t[3];
        g_part[b*3+0] = ti;
        g_part[b*3+1] = tp;
        g_part[b*3+2] = tt;
        __threadfence();
        int old = atomicAdd(&g_count, 1);
        s_last = (old == NBLOCKS - 1) ? 1 : 0;
    }
    __syncthreads();

    // ---- last block finalizes: per-instance dice + mean ----
    if (s_last) {
        float fi = 0.0f, fp = 0.0f, ft = 0.0f;   // instance = tid
#pragma unroll
        for (int c = 0; c < SPLIT; c++) {
            int slot = ((tid << 2) + c) * 3;
            fi += __ldcg(&g_part[slot+0]);
            fp += __ldcg(&g_part[slot+1]);
            ft += __ldcg(&g_part[slot+2]);
        }
        float loss = 1.0f - (2.0f*fi + 1.0f) / (fp + ft + 1.0f);
        s_vx[tid] = loss;                        // reuse smem as scratch
        __syncthreads();
        for (int o = THREADS/2; o > 0; o >>= 1) {
            if (tid < o) s_vx[tid] += s_vx[tid + o];
            __syncthreads();
        }
        if (tid == 0) {
            out[0] = s_vx[0] * (1.0f / (float)N_INST);
            g_count = 0;                          // reset for next graph replay
        }
    }
}

extern "C" void kernel_launch(void* const* d_in, const int* in_sizes, int n_in,
                              void* d_out, int out_size) {
    const float* preds  = (const float*)d_in[0];
    const float* masks  = (const float*)d_in[1];
    const float* bboxes = (const float*)d_in[2];
    float* out = (float*)d_out;

    fused_kernel<<<NBLOCKS, THREADS>>>(preds, masks, bboxes, out);
}